// round 11
// baseline (speedup 1.0000x reference)
#include <cuda_runtime.h>

#define NN 131072          // N_NODES
#define NG 512             // NUM_GRAPHS
#define FIN 54
#define HG 16
#define TLEN 1024
#define NCLS 192
#define EMAX 4194304

typedef unsigned long long ull;

// ------------------------- scratch (no cudaMalloc allowed) -------------------
__device__ __align__(16) int   g_degi[NN];
__device__ __align__(16) float g_dinv[NN];
__device__ __align__(16) int   g_eoff[NN];
__device__ __align__(16) int   g_ecur[NN];
__device__ __align__(16) int   g_part[512];
__device__ __align__(16) int   g_psum[512];
__device__ __align__(16) int2  g_epk[EMAX];                         // {src, dinv[src]}
__device__ __align__(16) float g_xw[NN * HG];
__device__ __align__(16) float g_agg[NN * HG];
__device__ __align__(16) int   g_starts[NG];
__device__ __align__(16) float g_seq0[(size_t)NG * TLEN * HG];      // 33.5 MB
__device__ __align__(16) float g_h0[(size_t)NG * TLEN * 64];        // 134 MB
__device__ __align__(16) float g_pre[(size_t)2 * NG * TLEN * 128];  // 537 MB
__device__ __align__(16) float g_pooled[NG * 64];

// ------------------------- helpers ------------------------------------------
__device__ __forceinline__ ull pk2(float lo, float hi) {
    ull v; asm("mov.b64 %0, {%1, %2};" : "=l"(v) : "f"(lo), "f"(hi)); return v;
}
__device__ __forceinline__ void upk2(ull v, float& lo, float& hi) {
    asm("mov.b64 {%0, %1}, %2;" : "=f"(lo), "=f"(hi) : "l"(v));
}
#define FMA2(d, a, b) asm("fma.rn.f32x2 %0, %1, %2, %0;" : "+l"(d) : "l"(a), "l"(b))

__device__ __forceinline__ float tanh_fast(float x) {
    float y; asm("tanh.approx.f32 %0, %1;" : "=f"(y) : "f"(x)); return y;
}
__device__ __forceinline__ float sig_fast(float x) {
    return fmaf(0.5f, tanh_fast(0.5f * x), 0.5f);
}
__device__ __forceinline__ unsigned tf32c(float x) {
    unsigned u; asm("cvt.rna.tf32.f32 %0, %1;" : "=r"(u) : "f"(x)); return u;
}

// ------------------------- init + degree + scan + fill -----------------------
__global__ void init_kernel() {
    int idx = blockIdx.x * 256 + threadIdx.x;
    if (idx < (int)(NG * TLEN * HG / 4))
        ((float4*)g_seq0)[idx] = make_float4(0.f, 0.f, 0.f, 0.f);
    if (idx < NN) g_degi[idx] = 0;
}

__global__ void deg_kernel(const int* __restrict__ dst, int E) {
    int e = blockIdx.x * 256 + threadIdx.x;
    if (e < E) atomicAdd(&g_degi[dst[e]], 1);
}

__global__ void scan1_kernel() {
    __shared__ int sh[256];
    int tid = threadIdx.x;
    sh[tid] = g_degi[blockIdx.x * 256 + tid];
    __syncthreads();
    for (int o = 128; o > 0; o >>= 1) {
        if (tid < o) sh[tid] += sh[tid + o];
        __syncthreads();
    }
    if (tid == 0) g_part[blockIdx.x] = sh[0];
}

__global__ void scan2_kernel() {
    __shared__ int sh[512];
    int tid = threadIdx.x;
    sh[tid] = g_part[tid];
    __syncthreads();
    int v;
    for (int o = 1; o < 512; o <<= 1) {
        v = (tid >= o) ? sh[tid - o] : 0;
        __syncthreads();
        sh[tid] += v;
        __syncthreads();
    }
    g_psum[tid] = (tid == 0) ? 0 : sh[tid - 1];
}

__global__ void scan3_kernel() {
    __shared__ int sh[256];
    int tid = threadIdx.x;
    int n = blockIdx.x * 256 + tid;
    int d = g_degi[n];
    sh[tid] = d;
    __syncthreads();
    int v;
    for (int o = 1; o < 256; o <<= 1) {
        v = (tid >= o) ? sh[tid - o] : 0;
        __syncthreads();
        sh[tid] += v;
        __syncthreads();
    }
    int off = g_psum[blockIdx.x] + sh[tid] - d;   // exclusive
    g_eoff[n] = off;
    g_ecur[n] = off;
    g_dinv[n] = rsqrtf((float)(d + 1));           // +1 self-loop
}

__global__ void fill_kernel(const int* __restrict__ src, const int* __restrict__ dst, int E) {
    int e = blockIdx.x * 256 + threadIdx.x;
    if (e >= E) return;
    int s = src[e], d = dst[e];
    int pos = atomicAdd(&g_ecur[d], 1);
    g_epk[pos] = make_int2(s, __float_as_int(g_dinv[s]));
}

// ------------------------- GCN feature transform -----------------------------
__global__ __launch_bounds__(256) void xw1_kernel(const float* __restrict__ x,
                                                  const float* __restrict__ W) {
    __shared__ float Ws[FIN * HG];
    __shared__ float Xs[16 * FIN];
    int tid = threadIdx.x;
    for (int i = tid; i < FIN * HG; i += 256) Ws[i] = W[i];
    size_t base = (size_t)blockIdx.x * 16 * FIN;
    for (int i = tid; i < 16 * FIN; i += 256) Xs[i] = x[base + i];
    __syncthreads();
    int nl = tid >> 4, j = tid & 15;
    const float* xr = Xs + nl * FIN;
    float acc = 0.f;
#pragma unroll
    for (int d = 0; d < FIN; d++) acc = fmaf(xr[d], Ws[d * HG + j], acc);
    g_xw[(size_t)blockIdx.x * 256 + tid] = acc;
}

__global__ __launch_bounds__(256) void xw2_kernel(const float* __restrict__ W) {
    __shared__ float Ws[HG * HG];
    __shared__ float Xs[16 * HG];
    int tid = threadIdx.x;
    if (tid < HG * HG) Ws[tid] = W[tid];
    size_t base = (size_t)blockIdx.x * 16 * HG;
    if (tid < 64) ((float4*)Xs)[tid] = ((const float4*)(g_agg + base))[tid];
    __syncthreads();
    int nl = tid >> 4, j = tid & 15;
    const float* xr = Xs + nl * HG;
    float acc = 0.f;
#pragma unroll
    for (int d = 0; d < HG; d++) acc = fmaf(fmaxf(xr[d], 0.f), Ws[d * HG + j], acc);
    g_xw[(size_t)blockIdx.x * 256 + tid] = acc;
}

// ------------------------- gather-based conv ---------------------------------
__global__ __launch_bounds__(256) void conv_kernel(const float* __restrict__ bias) {
    int n = blockIdx.x * 256 + threadIdx.x;
    if (n >= NN) return;
    int e0 = g_eoff[n];
    int e1 = e0 + g_degi[n];
    float4 a0 = make_float4(0.f, 0.f, 0.f, 0.f), a1 = a0, a2 = a0, a3 = a0;
#pragma unroll 4
    for (int e = e0; e < e1; e++) {
        int2 pk = g_epk[e];
        int s = pk.x;
        float nr = __int_as_float(pk.y);
        const float4* xs = (const float4*)(g_xw + (size_t)s * HG);
        float4 v0 = xs[0], v1 = xs[1], v2 = xs[2], v3 = xs[3];
        a0.x = fmaf(nr, v0.x, a0.x); a0.y = fmaf(nr, v0.y, a0.y);
        a0.z = fmaf(nr, v0.z, a0.z); a0.w = fmaf(nr, v0.w, a0.w);
        a1.x = fmaf(nr, v1.x, a1.x); a1.y = fmaf(nr, v1.y, a1.y);
        a1.z = fmaf(nr, v1.z, a1.z); a1.w = fmaf(nr, v1.w, a1.w);
        a2.x = fmaf(nr, v2.x, a2.x); a2.y = fmaf(nr, v2.y, a2.y);
        a2.z = fmaf(nr, v2.z, a2.z); a2.w = fmaf(nr, v2.w, a2.w);
        a3.x = fmaf(nr, v3.x, a3.x); a3.y = fmaf(nr, v3.y, a3.y);
        a3.z = fmaf(nr, v3.z, a3.z); a3.w = fmaf(nr, v3.w, a3.w);
    }
    float di = g_dinv[n];
    float d2 = di * di;
    const float4* xn = (const float4*)(g_xw + (size_t)n * HG);
    const float4* bb = (const float4*)bias;
    float4* out = (float4*)(g_agg + (size_t)n * HG);
    float4 q, b, w;
#define EMIT(acc, k) \
    w = xn[k]; b = bb[k]; \
    q.x = b.x + di * acc.x + d2 * w.x; q.y = b.y + di * acc.y + d2 * w.y; \
    q.z = b.z + di * acc.z + d2 * w.z; q.w = b.w + di * acc.w + d2 * w.w; \
    out[k] = q;
    EMIT(a0, 0) EMIT(a1, 1) EMIT(a2, 2) EMIT(a3, 3)
#undef EMIT
}

// ------------------------- ragged -> padded ---------------------------------
__global__ void starts_kernel(const int* __restrict__ batch) {
    int i = blockIdx.x * 256 + threadIdx.x;
    if (i >= NN) return;
    int b = batch[i];
    int bp = (i == 0) ? -1 : batch[i - 1];
    for (int g = bp + 1; g <= b; ++g) g_starts[g] = i;   // batch is sorted
}

__global__ void pack_kernel(const int* __restrict__ batch) {
    int idx = blockIdx.x * 256 + threadIdx.x;
    if (idx >= NN * 4) return;
    int n = idx >> 2, q = idx & 3;
    int g = batch[n];
    int pos = n - g_starts[g];
    if (pos >= TLEN) return;  // mode="drop"
    float4 v = ((const float4*)(g_agg + (size_t)n * HG))[q];
    v.x = fmaxf(v.x, 0.f); v.y = fmaxf(v.y, 0.f);
    v.z = fmaxf(v.z, 0.f); v.w = fmaxf(v.w, 0.f);
    ((float4*)(g_seq0 + ((size_t)g * TLEN + pos) * HG))[q] = v;
}

// ------------------------- LSTM input projection: tf32 tensor-core GEMM ------
// pre[dir][row][t][p] with p = unit*4 + gate; C = X[128t x K] * Wp[K x 128] + b
// Block: 256 thr (8 warps), tile 128 timesteps x 128 gates; warp w owns rows
// [16w,16w+16). Weight cols permuted in smem so mma n-index == memory index.
template<int DIN>
__global__ __launch_bounds__(256) void gemm_mma_kernel(
    const float* __restrict__ X,      // [NG][TLEN][DIN]
    const float* __restrict__ wih,    // [2][128][DIN]
    const float* __restrict__ bih, const float* __restrict__ bhh)
{
    constexpr int XS = DIN + 4;       // X smem stride (bank-conflict free frags)
    constexpr int WS = 132;           // W smem stride
    constexpr int KC = DIN / 8;       // k-chunks of 8
    extern __shared__ unsigned dsm[];
    unsigned* Ws = dsm;                         // [DIN][WS] tf32, permuted cols
    unsigned* Xs = dsm + DIN * WS;              // [128][XS] tf32
    float*    Bs = (float*)(Xs + 128 * XS);     // [128]

    int dir = blockIdx.z, row = blockIdx.y, tb = blockIdx.x * 128;
    int tid = threadIdx.x;

    // stage W (permuted: col p = j*4+g  <-  wih row g*32+j), convert to tf32
    {
        int p = tid & 127, half = tid >> 7;
        int j = p >> 2, gg = p & 3;
        const float4* wr = (const float4*)(wih + ((size_t)dir * 128 + gg * 32 + j) * DIN);
        constexpr int K4H = DIN / 8;  // float4s per half
#pragma unroll
        for (int q = 0; q < K4H; q++) {
            int k4 = half * K4H + q;
            float4 v = wr[k4];
            int k = k4 * 4;
            Ws[(k + 0) * WS + p] = tf32c(v.x);
            Ws[(k + 1) * WS + p] = tf32c(v.y);
            Ws[(k + 2) * WS + p] = tf32c(v.z);
            Ws[(k + 3) * WS + p] = tf32c(v.w);
        }
        if (tid < 128) Bs[p] = bih[dir * 128 + gg * 32 + j] + bhh[dir * 128 + gg * 32 + j];
    }
    // stage X, convert to tf32
    {
        const float4* Xg = (const float4*)(X + ((size_t)row * TLEN + tb) * DIN);
#pragma unroll
        for (int i = tid; i < 128 * DIN / 4; i += 256) {
            float4 v = Xg[i];
            int r = (i * 4) / DIN, k = (i * 4) % DIN;
            unsigned* xp = Xs + r * XS + k;
            xp[0] = tf32c(v.x); xp[1] = tf32c(v.y);
            xp[2] = tf32c(v.z); xp[3] = tf32c(v.w);
        }
    }
    __syncthreads();

    int w = tid >> 5, lane = tid & 31;
    int qr = lane >> 2, m = lane & 3;

    float c[16][4];
#pragma unroll
    for (int nt = 0; nt < 16; nt++) {
        c[nt][0] = 0.f; c[nt][1] = 0.f; c[nt][2] = 0.f; c[nt][3] = 0.f;
    }

    const unsigned* xrow0 = Xs + (w * 16 + qr) * XS;
    const unsigned* xrow1 = xrow0 + 8 * XS;

#pragma unroll
    for (int kc = 0; kc < KC; kc++) {
        int k0 = kc * 8;
        unsigned a0 = xrow0[k0 + m];
        unsigned a1 = xrow1[k0 + m];
        unsigned a2 = xrow0[k0 + m + 4];
        unsigned a3 = xrow1[k0 + m + 4];
        const unsigned* wb0 = Ws + (k0 + m) * WS + qr;
        const unsigned* wb1 = wb0 + 4 * WS;
#pragma unroll
        for (int nt = 0; nt < 16; nt++) {
            unsigned b0 = wb0[nt * 8], b1 = wb1[nt * 8];
            asm volatile(
                "mma.sync.aligned.m16n8k8.row.col.f32.tf32.tf32.f32 "
                "{%0,%1,%2,%3}, {%4,%5,%6,%7}, {%8,%9}, {%0,%1,%2,%3};"
                : "+f"(c[nt][0]), "+f"(c[nt][1]), "+f"(c[nt][2]), "+f"(c[nt][3])
                : "r"(a0), "r"(a1), "r"(a2), "r"(a3), "r"(b0), "r"(b1));
        }
    }

    // epilogue: + bias, direct store into interleaved layout
    float* Og = g_pre + (((size_t)dir * NG + row) * TLEN + tb) * 128;
    int r0 = w * 16 + qr;
#pragma unroll
    for (int nt = 0; nt < 16; nt++) {
        int p0 = nt * 8 + m * 2;
        float2 bb = *(const float2*)(Bs + p0);
        float2 v0 = make_float2(c[nt][0] + bb.x, c[nt][1] + bb.y);
        float2 v1 = make_float2(c[nt][2] + bb.x, c[nt][3] + bb.y);
        *(float2*)(Og + (size_t)r0 * 128 + p0) = v0;
        *(float2*)(Og + (size_t)(r0 + 8) * 128 + p0) = v1;
    }
}

// ------------------------- LSTM recurrence -----------------------------------
template<bool IS_L0>
__global__ __launch_bounds__(32) void lstm_rec_kernel(const float* __restrict__ whh)
{
    int row = blockIdx.x, dir = blockIdx.y;
    int j = threadIdx.x;
    const float4* P = (const float4*)(g_pre + ((size_t)dir * NG + row) * TLEN * 128) + j;
    float* O = g_h0 + (size_t)row * TLEN * 64 + dir * 32 + j;

    ulonglong2 w[4][8];
#pragma unroll
    for (int g = 0; g < 4; g++) {
        const ulonglong2* wp = (const ulonglong2*)(whh + ((size_t)dir * 128 + g * 32 + j) * 32);
#pragma unroll
        for (int q = 0; q < 8; q++) w[g][q] = wp[q];
    }

    __shared__ __align__(16) float h_s[2][32];
    h_s[0][j] = 0.f;
    __syncwarp();

    int t0 = dir ? (TLEN - 1) : 0;
    int dt = dir ? -1 : 1;
    float c = 0.f, pool = 0.f;
    int buf = 0;

#define LOADP(s_) P[(size_t)(t0 + (s_) * dt) * 32]

#define STEP(pp, s_) { \
    ull a0 = pk2(pp.x, 0.f), a1 = pk2(pp.y, 0.f); \
    ull a2 = pk2(pp.z, 0.f), a3 = pk2(pp.w, 0.f); \
    const ulonglong2* hv = (const ulonglong2*)h_s[buf]; \
    _Pragma("unroll") \
    for (int q = 0; q < 8; q++) { \
        ulonglong2 hh = hv[q]; \
        FMA2(a0, hh.x, w[0][q].x); FMA2(a0, hh.y, w[0][q].y); \
        FMA2(a1, hh.x, w[1][q].x); FMA2(a1, hh.y, w[1][q].y); \
        FMA2(a2, hh.x, w[2][q].x); FMA2(a2, hh.y, w[2][q].y); \
        FMA2(a3, hh.x, w[3][q].x); FMA2(a3, hh.y, w[3][q].y); \
    } \
    float lo, hi; \
    upk2(a0, lo, hi); float gi = sig_fast(lo + hi); \
    upk2(a1, lo, hi); float gf = sig_fast(lo + hi); \
    upk2(a2, lo, hi); float gg = tanh_fast(lo + hi); \
    upk2(a3, lo, hi); float go = sig_fast(lo + hi); \
    c = gf * c + gi * gg; \
    float h = go * tanh_fast(c); \
    if (IS_L0) O[(size_t)(t0 + (s_) * dt) * 64] = h; \
    else       pool += h; \
    h_s[buf ^ 1][j] = h; \
    __syncwarp(); \
    buf ^= 1; }

    float4 p0 = LOADP(0);
    float4 p1 = LOADP(1);
    float4 p2 = LOADP(2);
    for (int s = 0; s < TLEN; s += 4) {
        float4 p3 = (s + 3 < TLEN) ? LOADP(s + 3) : p0;
        STEP(p0, s)
        float4 q0 = (s + 4 < TLEN) ? LOADP(s + 4) : p0;
        STEP(p1, s + 1)
        float4 q1 = (s + 5 < TLEN) ? LOADP(s + 5) : p0;
        STEP(p2, s + 2)
        float4 q2 = (s + 6 < TLEN) ? LOADP(s + 6) : p0;
        STEP(p3, s + 3)
        p0 = q0; p1 = q1; p2 = q2;
    }
#undef STEP
#undef LOADP
    if (!IS_L0) g_pooled[row * 64 + dir * 32 + j] = pool;
}

// ------------------------- FC + mean ----------------------------------------
__global__ void fc_kernel(const float* __restrict__ w, const float* __restrict__ b,
                          float* __restrict__ out) {
    int idx = blockIdx.x * 256 + threadIdx.x;
    if (idx >= NG * NCLS) return;
    int r = idx / NCLS, cc = idx - r * NCLS;
    const float* p = g_pooled + r * 64;
    float acc = 0.f;
#pragma unroll
    for (int k = 0; k < 64; k++) acc += p[k] * w[k * NCLS + cc];
    out[idx] = b[cc] + acc * (1.f / (float)TLEN);
}

// ------------------------- launch -------------------------------------------
extern "C" void kernel_launch(void* const* d_in, const int* in_sizes, int n_in,
                              void* d_out, int out_size) {
    const float* x     = (const float*)d_in[0];
    const int*   ei    = (const int*)d_in[1];
    const int*   batch = (const int*)d_in[2];
    const float* w1    = (const float*)d_in[3];
    const float* b1    = (const float*)d_in[4];
    const float* w2    = (const float*)d_in[5];
    const float* b2    = (const float*)d_in[6];
    const float* l0wih = (const float*)d_in[7];
    const float* l0whh = (const float*)d_in[8];
    const float* l0bih = (const float*)d_in[9];
    const float* l0bhh = (const float*)d_in[10];
    const float* l1wih = (const float*)d_in[11];
    const float* l1whh = (const float*)d_in[12];
    const float* l1bih = (const float*)d_in[13];
    const float* l1bhh = (const float*)d_in[14];
    const float* fcw   = (const float*)d_in[15];
    const float* fcb   = (const float*)d_in[16];
    float* out = (float*)d_out;

    int E = in_sizes[1] / 2;
    const int* src = ei;
    const int* dst = ei + E;

    float* seq0_p; cudaGetSymbolAddress((void**)&seq0_p, g_seq0);
    float* h0_p;   cudaGetSymbolAddress((void**)&h0_p, g_h0);

    // dynamic smem opt-in for the mma GEMMs (idempotent host config, no alloc)
    const int SM16 = (16 * 132 + 128 * 20 + 128) * 4;   // 19200 B
    const int SM64 = (64 * 132 + 128 * 68 + 128) * 4;   // 69120 B
    cudaFuncSetAttribute(gemm_mma_kernel<16>, cudaFuncAttributeMaxDynamicSharedMemorySize, SM16);
    cudaFuncSetAttribute(gemm_mma_kernel<64>, cudaFuncAttributeMaxDynamicSharedMemorySize, SM64);

    // CSR build
    init_kernel<<<8192, 256>>>();                          // launch 0
    deg_kernel<<<(E + 255) / 256, 256>>>(dst, E);          // launch 1
    scan1_kernel<<<512, 256>>>();                          // launch 2

    // PROBE (launch 3 = the one ncu profiles): 1/16-scale conv_kernel using
    // the (stale-but-deterministic) CSR + xw from the previous iteration; its
    // g_agg writes are fully overwritten by the real convs below. First-call
    // state is all-zeros (deg fresh but eoff/epk zero -> reads epk[0..deg),
    // in-bounds, result overwritten). Measures GCN gather roofline.
    conv_kernel<<<32, 256>>>(b1);

    scan2_kernel<<<1, 512>>>();                            // launch 4
    scan3_kernel<<<512, 256>>>();                          // launch 5
    fill_kernel<<<(E + 255) / 256, 256>>>(src, dst, E);

    // conv1 + conv2 (gather-based)
    xw1_kernel<<<NN / 16, 256>>>(x, w1);
    conv_kernel<<<NN / 256, 256>>>(b1);
    xw2_kernel<<<NN / 16, 256>>>(w2);
    conv_kernel<<<NN / 256, 256>>>(b2);

    // pack
    starts_kernel<<<(NN + 255) / 256, 256>>>(batch);
    pack_kernel<<<(NN * 4 + 255) / 256, 256>>>(batch);

    // BiLSTM layer 0 (tf32 tensor-core input projection + 1-warp recurrence)
    gemm_mma_kernel<16><<<dim3(TLEN / 128, NG, 2), 256, SM16>>>(seq0_p, l0wih, l0bih, l0bhh);
    lstm_rec_kernel<true><<<dim3(NG, 2), 32>>>(l0whh);

    // BiLSTM layer 1 (fuses mean pooling)
    gemm_mma_kernel<64><<<dim3(TLEN / 128, NG, 2), 256, SM64>>>(h0_p, l1wih, l1bih, l1bhh);
    lstm_rec_kernel<false><<<dim3(NG, 2), 32>>>(l1whh);

    fc_kernel<<<(NG * NCLS + 255) / 256, 256>>>(fcw, fcb, out);
}

// round 14
// speedup vs baseline: 1.1178x; 1.1178x over previous
#include <cuda_runtime.h>

#define NN 131072          // N_NODES
#define NG 512             // NUM_GRAPHS
#define FIN 54
#define HG 16
#define TLEN 1024
#define NCLS 192
#define EMAX 4194304

typedef unsigned long long ull;

// ------------------------- scratch (no cudaMalloc allowed) -------------------
__device__ __align__(16) int   g_degi[NN];
__device__ __align__(16) float g_dinv[NN];
__device__ __align__(16) int   g_eoff[NN];
__device__ __align__(16) int   g_ecur[NN];
__device__ __align__(16) int   g_part[512];
__device__ __align__(16) int   g_psum[512];
__device__ __align__(16) int2  g_epk[EMAX];                         // {src, dinv[src]}
__device__ __align__(16) float g_xw[NN * HG];
__device__ __align__(16) float g_agg[NN * HG];
__device__ __align__(16) int   g_starts[NG];
__device__ __align__(16) float g_seq0[(size_t)NG * TLEN * HG];      // 33.5 MB
__device__ __align__(16) float g_h0[(size_t)NG * TLEN * 64];        // 134 MB
__device__ __align__(16) float g_pre[(size_t)2 * NG * TLEN * 128];  // 537 MB
__device__ __align__(16) float g_pooled[NG * 64];

// ------------------------- helpers ------------------------------------------
__device__ __forceinline__ ull pk2(float lo, float hi) {
    ull v; asm("mov.b64 %0, {%1, %2};" : "=l"(v) : "f"(lo), "f"(hi)); return v;
}
__device__ __forceinline__ void upk2(ull v, float& lo, float& hi) {
    asm("mov.b64 {%0, %1}, %2;" : "=f"(lo), "=f"(hi) : "l"(v));
}
#define FMA2(d, a, b) asm("fma.rn.f32x2 %0, %1, %2, %0;" : "+l"(d) : "l"(a), "l"(b))

__device__ __forceinline__ float tanh_fast(float x) {
    float y; asm("tanh.approx.f32 %0, %1;" : "=f"(y) : "f"(x)); return y;
}
__device__ __forceinline__ float sig_fast(float x) {
    return fmaf(0.5f, tanh_fast(0.5f * x), 0.5f);
}

// ------------------------- init + degree + scan + fill -----------------------
__global__ void init_kernel() {
    int idx = blockIdx.x * 256 + threadIdx.x;
    if (idx < (int)(NG * TLEN * HG / 4))
        ((float4*)g_seq0)[idx] = make_float4(0.f, 0.f, 0.f, 0.f);
    if (idx < NN) g_degi[idx] = 0;
}

__global__ void deg_kernel(const int* __restrict__ dst, int E) {
    int e = blockIdx.x * 256 + threadIdx.x;
    if (e < E) atomicAdd(&g_degi[dst[e]], 1);
}

__global__ void scan1_kernel() {
    __shared__ int sh[256];
    int tid = threadIdx.x;
    sh[tid] = g_degi[blockIdx.x * 256 + tid];
    __syncthreads();
    for (int o = 128; o > 0; o >>= 1) {
        if (tid < o) sh[tid] += sh[tid + o];
        __syncthreads();
    }
    if (tid == 0) g_part[blockIdx.x] = sh[0];
}

__global__ void scan2_kernel() {
    __shared__ int sh[512];
    int tid = threadIdx.x;
    sh[tid] = g_part[tid];
    __syncthreads();
    int v;
    for (int o = 1; o < 512; o <<= 1) {
        v = (tid >= o) ? sh[tid - o] : 0;
        __syncthreads();
        sh[tid] += v;
        __syncthreads();
    }
    g_psum[tid] = (tid == 0) ? 0 : sh[tid - 1];
}

__global__ void scan3_kernel() {
    __shared__ int sh[256];
    int tid = threadIdx.x;
    int n = blockIdx.x * 256 + tid;
    int d = g_degi[n];
    sh[tid] = d;
    __syncthreads();
    int v;
    for (int o = 1; o < 256; o <<= 1) {
        v = (tid >= o) ? sh[tid - o] : 0;
        __syncthreads();
        sh[tid] += v;
        __syncthreads();
    }
    int off = g_psum[blockIdx.x] + sh[tid] - d;   // exclusive
    g_eoff[n] = off;
    g_ecur[n] = off;
    g_dinv[n] = rsqrtf((float)(d + 1));           // +1 self-loop
}

__global__ void fill_kernel(const int* __restrict__ src, const int* __restrict__ dst, int E) {
    int e = blockIdx.x * 256 + threadIdx.x;
    if (e >= E) return;
    int s = src[e], d = dst[e];
    int pos = atomicAdd(&g_ecur[d], 1);
    g_epk[pos] = make_int2(s, __float_as_int(g_dinv[s]));
}

// ------------------------- GCN feature transform -----------------------------
__global__ __launch_bounds__(256) void xw1_kernel(const float* __restrict__ x,
                                                  const float* __restrict__ W) {
    __shared__ float Ws[FIN * HG];
    __shared__ float Xs[16 * FIN];
    int tid = threadIdx.x;
    for (int i = tid; i < FIN * HG; i += 256) Ws[i] = W[i];
    size_t base = (size_t)blockIdx.x * 16 * FIN;
    for (int i = tid; i < 16 * FIN; i += 256) Xs[i] = x[base + i];
    __syncthreads();
    int nl = tid >> 4, j = tid & 15;
    const float* xr = Xs + nl * FIN;
    float acc = 0.f;
#pragma unroll
    for (int d = 0; d < FIN; d++) acc = fmaf(xr[d], Ws[d * HG + j], acc);
    g_xw[(size_t)blockIdx.x * 256 + tid] = acc;
}

__global__ __launch_bounds__(256) void xw2_kernel(const float* __restrict__ W) {
    __shared__ float Ws[HG * HG];
    __shared__ float Xs[16 * HG];
    int tid = threadIdx.x;
    if (tid < HG * HG) Ws[tid] = W[tid];
    size_t base = (size_t)blockIdx.x * 16 * HG;
    if (tid < 64) ((float4*)Xs)[tid] = ((const float4*)(g_agg + base))[tid];
    __syncthreads();
    int nl = tid >> 4, j = tid & 15;
    const float* xr = Xs + nl * HG;
    float acc = 0.f;
#pragma unroll
    for (int d = 0; d < HG; d++) acc = fmaf(fmaxf(xr[d], 0.f), Ws[d * HG + j], acc);
    g_xw[(size_t)blockIdx.x * 256 + tid] = acc;
}

// ------------------------- gather-based conv (2 threads per node) ------------
// Pair of adjacent threads splits a node's edge list (interleaved); partial
// sums combined via shfl_xor(1). Doubles warp-level MLP, halves tail.
__global__ __launch_bounds__(256) void conv_kernel(const float* __restrict__ bias) {
    int idx = blockIdx.x * 256 + threadIdx.x;
    int n = idx >> 1, par = idx & 1;
    if (n >= NN) return;
    int e0 = g_eoff[n];
    int e1 = e0 + g_degi[n];
    float4 a0 = make_float4(0.f, 0.f, 0.f, 0.f), a1 = a0, a2 = a0, a3 = a0;
#pragma unroll 4
    for (int e = e0 + par; e < e1; e += 2) {
        int2 pk = g_epk[e];
        int s = pk.x;
        float nr = __int_as_float(pk.y);
        const float4* xs = (const float4*)(g_xw + (size_t)s * HG);
        float4 v0 = xs[0], v1 = xs[1], v2 = xs[2], v3 = xs[3];
        a0.x = fmaf(nr, v0.x, a0.x); a0.y = fmaf(nr, v0.y, a0.y);
        a0.z = fmaf(nr, v0.z, a0.z); a0.w = fmaf(nr, v0.w, a0.w);
        a1.x = fmaf(nr, v1.x, a1.x); a1.y = fmaf(nr, v1.y, a1.y);
        a1.z = fmaf(nr, v1.z, a1.z); a1.w = fmaf(nr, v1.w, a1.w);
        a2.x = fmaf(nr, v2.x, a2.x); a2.y = fmaf(nr, v2.y, a2.y);
        a2.z = fmaf(nr, v2.z, a2.z); a2.w = fmaf(nr, v2.w, a2.w);
        a3.x = fmaf(nr, v3.x, a3.x); a3.y = fmaf(nr, v3.y, a3.y);
        a3.z = fmaf(nr, v3.z, a3.z); a3.w = fmaf(nr, v3.w, a3.w);
    }
#define CMB(f) f += __shfl_xor_sync(0xffffffffu, f, 1)
    CMB(a0.x); CMB(a0.y); CMB(a0.z); CMB(a0.w);
    CMB(a1.x); CMB(a1.y); CMB(a1.z); CMB(a1.w);
    CMB(a2.x); CMB(a2.y); CMB(a2.z); CMB(a2.w);
    CMB(a3.x); CMB(a3.y); CMB(a3.z); CMB(a3.w);
#undef CMB
    if (par) return;
    float di = g_dinv[n];
    float d2 = di * di;
    const float4* xn = (const float4*)(g_xw + (size_t)n * HG);
    const float4* bb = (const float4*)bias;
    float4* out = (float4*)(g_agg + (size_t)n * HG);
    float4 q, b, w;
#define EMIT(acc, k) \
    w = xn[k]; b = bb[k]; \
    q.x = b.x + di * acc.x + d2 * w.x; q.y = b.y + di * acc.y + d2 * w.y; \
    q.z = b.z + di * acc.z + d2 * w.z; q.w = b.w + di * acc.w + d2 * w.w; \
    out[k] = q;
    EMIT(a0, 0) EMIT(a1, 1) EMIT(a2, 2) EMIT(a3, 3)
#undef EMIT
}

// ------------------------- ragged -> padded ---------------------------------
__global__ void starts_kernel(const int* __restrict__ batch) {
    int i = blockIdx.x * 256 + threadIdx.x;
    if (i >= NN) return;
    int b = batch[i];
    int bp = (i == 0) ? -1 : batch[i - 1];
    for (int g = bp + 1; g <= b; ++g) g_starts[g] = i;   // batch is sorted
}

__global__ void pack_kernel(const int* __restrict__ batch) {
    int idx = blockIdx.x * 256 + threadIdx.x;
    if (idx >= NN * 4) return;
    int n = idx >> 2, q = idx & 3;
    int g = batch[n];
    int pos = n - g_starts[g];
    if (pos >= TLEN) return;  // mode="drop"
    float4 v = ((const float4*)(g_agg + (size_t)n * HG))[q];
    v.x = fmaxf(v.x, 0.f); v.y = fmaxf(v.y, 0.f);
    v.z = fmaxf(v.z, 0.f); v.w = fmaxf(v.w, 0.f);
    ((float4*)(g_seq0 + ((size_t)g * TLEN + pos) * HG))[q] = v;
}

// ------------------------- LSTM input projection: register-W GEMM ------------
// 128 threads; thread p owns output column p = unit*4 + gate of the
// interleaved pre layout, i.e. wih row r = gate*32 + unit. The whole W row
// lives in registers; X is staged once per block and read as warp-broadcast
// LDS.128; stores are stride-1 coalesced STG.32.
template<int DIN, int TT>
__global__ __launch_bounds__(128) void gemm_reg_kernel(
    const float* __restrict__ X,      // [NG][TLEN][DIN]
    const float* __restrict__ wih,    // [2][128][DIN]
    const float* __restrict__ bih, const float* __restrict__ bhh)
{
    extern __shared__ float xs[];     // [TT * DIN]
    int dir = blockIdx.z, row = blockIdx.y, tb = blockIdx.x * TT;
    int p = threadIdx.x;
    int g = p & 3, j = p >> 2;
    int r = g * 32 + j;

    ull w[DIN / 2];
    {
        const ull* wp = (const ull*)(wih + ((size_t)dir * 128 + r) * DIN);
#pragma unroll
        for (int k = 0; k < DIN / 2; k++) w[k] = wp[k];
    }
    float bias = bih[dir * 128 + r] + bhh[dir * 128 + r];

    {
        const float4* Xg = (const float4*)(X + ((size_t)row * TLEN + tb) * DIN);
#pragma unroll
        for (int i = p; i < TT * DIN / 4; i += 128) ((float4*)xs)[i] = Xg[i];
    }
    __syncthreads();

    float* Og = g_pre + (((size_t)dir * NG + row) * TLEN + tb) * 128 + p;

#pragma unroll 1
    for (int t = 0; t < TT; t += 8) {
        ull acc[8];
#pragma unroll
        for (int u = 0; u < 8; u++) acc[u] = 0ull;
#pragma unroll
        for (int kc = 0; kc < DIN / 8; kc++) {
#pragma unroll
            for (int u = 0; u < 8; u++) {
                const ulonglong2* xp = (const ulonglong2*)(xs + (t + u) * DIN + kc * 8);
                ulonglong2 xa = xp[0];
                ulonglong2 xb = xp[1];
                FMA2(acc[u], xa.x, w[kc * 4 + 0]);
                FMA2(acc[u], xa.y, w[kc * 4 + 1]);
                FMA2(acc[u], xb.x, w[kc * 4 + 2]);
                FMA2(acc[u], xb.y, w[kc * 4 + 3]);
            }
        }
#pragma unroll
        for (int u = 0; u < 8; u++) {
            float lo, hi; upk2(acc[u], lo, hi);
            Og[(size_t)(t + u) * 128] = lo + hi + bias;
        }
    }
}

// ------------------------- LSTM recurrence -----------------------------------
template<bool IS_L0>
__global__ __launch_bounds__(32) void lstm_rec_kernel(const float* __restrict__ whh)
{
    int row = blockIdx.x, dir = blockIdx.y;
    int j = threadIdx.x;
    const float4* P = (const float4*)(g_pre + ((size_t)dir * NG + row) * TLEN * 128) + j;
    float* O = g_h0 + (size_t)row * TLEN * 64 + dir * 32 + j;

    ulonglong2 w[4][8];
#pragma unroll
    for (int g = 0; g < 4; g++) {
        const ulonglong2* wp = (const ulonglong2*)(whh + ((size_t)dir * 128 + g * 32 + j) * 32);
#pragma unroll
        for (int q = 0; q < 8; q++) w[g][q] = wp[q];
    }

    __shared__ __align__(16) float h_s[2][32];
    h_s[0][j] = 0.f;
    __syncwarp();

    int t0 = dir ? (TLEN - 1) : 0;
    int dt = dir ? -1 : 1;
    float c = 0.f, pool = 0.f;
    int buf = 0;

#define LOADP(s_) P[(size_t)(t0 + (s_) * dt) * 32]

#define STEP(pp, s_) { \
    ull a0 = pk2(pp.x, 0.f), a1 = pk2(pp.y, 0.f); \
    ull a2 = pk2(pp.z, 0.f), a3 = pk2(pp.w, 0.f); \
    const ulonglong2* hv = (const ulonglong2*)h_s[buf]; \
    _Pragma("unroll") \
    for (int q = 0; q < 8; q++) { \
        ulonglong2 hh = hv[q]; \
        FMA2(a0, hh.x, w[0][q].x); FMA2(a0, hh.y, w[0][q].y); \
        FMA2(a1, hh.x, w[1][q].x); FMA2(a1, hh.y, w[1][q].y); \
        FMA2(a2, hh.x, w[2][q].x); FMA2(a2, hh.y, w[2][q].y); \
        FMA2(a3, hh.x, w[3][q].x); FMA2(a3, hh.y, w[3][q].y); \
    } \
    float lo, hi; \
    upk2(a0, lo, hi); float gi = sig_fast(lo + hi); \
    upk2(a1, lo, hi); float gf = sig_fast(lo + hi); \
    upk2(a2, lo, hi); float gg = tanh_fast(lo + hi); \
    upk2(a3, lo, hi); float go = sig_fast(lo + hi); \
    c = gf * c + gi * gg; \
    float h = go * tanh_fast(c); \
    if (IS_L0) O[(size_t)(t0 + (s_) * dt) * 64] = h; \
    else       pool += h; \
    h_s[buf ^ 1][j] = h; \
    __syncwarp(); \
    buf ^= 1; }

    float4 p0 = LOADP(0);
    float4 p1 = LOADP(1);
    float4 p2 = LOADP(2);
    for (int s = 0; s < TLEN; s += 4) {
        float4 p3 = (s + 3 < TLEN) ? LOADP(s + 3) : p0;
        STEP(p0, s)
        float4 q0 = (s + 4 < TLEN) ? LOADP(s + 4) : p0;
        STEP(p1, s + 1)
        float4 q1 = (s + 5 < TLEN) ? LOADP(s + 5) : p0;
        STEP(p2, s + 2)
        float4 q2 = (s + 6 < TLEN) ? LOADP(s + 6) : p0;
        STEP(p3, s + 3)
        p0 = q0; p1 = q1; p2 = q2;
    }
#undef STEP
#undef LOADP
    if (!IS_L0) g_pooled[row * 64 + dir * 32 + j] = pool;
}

// ------------------------- FC + mean ----------------------------------------
__global__ void fc_kernel(const float* __restrict__ w, const float* __restrict__ b,
                          float* __restrict__ out) {
    int idx = blockIdx.x * 256 + threadIdx.x;
    if (idx >= NG * NCLS) return;
    int r = idx / NCLS, cc = idx - r * NCLS;
    const float* p = g_pooled + r * 64;
    float acc = 0.f;
#pragma unroll
    for (int k = 0; k < 64; k++) acc += p[k] * w[k * NCLS + cc];
    out[idx] = b[cc] + acc * (1.f / (float)TLEN);
}

// ------------------------- launch -------------------------------------------
extern "C" void kernel_launch(void* const* d_in, const int* in_sizes, int n_in,
                              void* d_out, int out_size) {
    const float* x     = (const float*)d_in[0];
    const int*   ei    = (const int*)d_in[1];
    const int*   batch = (const int*)d_in[2];
    const float* w1    = (const float*)d_in[3];
    const float* b1    = (const float*)d_in[4];
    const float* w2    = (const float*)d_in[5];
    const float* b2    = (const float*)d_in[6];
    const float* l0wih = (const float*)d_in[7];
    const float* l0whh = (const float*)d_in[8];
    const float* l0bih = (const float*)d_in[9];
    const float* l0bhh = (const float*)d_in[10];
    const float* l1wih = (const float*)d_in[11];
    const float* l1whh = (const float*)d_in[12];
    const float* l1bih = (const float*)d_in[13];
    const float* l1bhh = (const float*)d_in[14];
    const float* fcw   = (const float*)d_in[15];
    const float* fcb   = (const float*)d_in[16];
    float* out = (float*)d_out;

    int E = in_sizes[1] / 2;
    const int* src = ei;
    const int* dst = ei + E;

    float* seq0_p; cudaGetSymbolAddress((void**)&seq0_p, g_seq0);
    float* h0_p;   cudaGetSymbolAddress((void**)&h0_p, g_h0);

    const int SMX64 = 128 * 64 * 4;   // 32 KB X tile (TT=128, DIN=64)
    const int SMX16 = 256 * 16 * 4;   // 16 KB X tile (TT=256, DIN=16)

    // CSR build
    init_kernel<<<8192, 256>>>();                          // launch 0
    deg_kernel<<<(E + 255) / 256, 256>>>(dst, E);          // launch 1
    scan1_kernel<<<512, 256>>>();                          // launch 2

    // PROBE (launch 3 = the one ncu profiles): 1/16-scale gemm_reg<64> on
    // stale-but-deterministic g_h0; its g_pre output region is fully
    // overwritten by the real gemm below. Measures the new GEMM's roofline.
    gemm_reg_kernel<64, 128><<<dim3(8, 32, 1), 128, SMX64>>>(h0_p, l1wih, l1bih, l1bhh);

    scan2_kernel<<<1, 512>>>();                            // launch 4
    scan3_kernel<<<512, 256>>>();                          // launch 5
    fill_kernel<<<(E + 255) / 256, 256>>>(src, dst, E);

    // conv1 + conv2 (gather-based, 2 threads/node)
    xw1_kernel<<<NN / 16, 256>>>(x, w1);
    conv_kernel<<<NN * 2 / 256, 256>>>(b1);
    xw2_kernel<<<NN / 16, 256>>>(w2);
    conv_kernel<<<NN * 2 / 256, 256>>>(b2);

    // pack
    starts_kernel<<<(NN + 255) / 256, 256>>>(batch);
    pack_kernel<<<(NN * 4 + 255) / 256, 256>>>(batch);

    // BiLSTM layer 0 (register-W GEMM + 1-warp recurrence)
    gemm_reg_kernel<16, 256><<<dim3(TLEN / 256, NG, 2), 128, SMX16>>>(seq0_p, l0wih, l0bih, l0bhh);
    lstm_rec_kernel<true><<<dim3(NG, 2), 32>>>(l0whh);

    // BiLSTM layer 1 (fuses mean pooling)
    gemm_reg_kernel<64, 128><<<dim3(TLEN / 128, NG, 2), 128, SMX64>>>(h0_p, l1wih, l1bih, l1bhh);
    lstm_rec_kernel<false><<<dim3(NG, 2), 32>>>(l1whh);

    fc_kernel<<<(NG * NCLS + 255) / 256, 256>>>(fcw, fcb, out);
}

// round 15
// speedup vs baseline: 1.2231x; 1.0942x over previous
#include <cuda_runtime.h>

#define NN 131072          // N_NODES
#define NG 512             // NUM_GRAPHS
#define FIN 54
#define HG 16
#define TLEN 1024
#define NCLS 192
#define EMAX 4194304

typedef unsigned long long ull;

// ------------------------- scratch (no cudaMalloc allowed) -------------------
__device__ __align__(16) int   g_degi[NN];
__device__ __align__(16) float g_dinv[NN];
__device__ __align__(16) int   g_eoff[NN];
__device__ __align__(16) int   g_ecur[NN];
__device__ __align__(16) int   g_part[512];
__device__ __align__(16) int   g_psum[512];
__device__ __align__(16) int2  g_epk[EMAX];                         // {src, dinv[src]}
__device__ __align__(16) float g_xw[NN * HG];
__device__ __align__(16) float g_agg[NN * HG];
__device__ __align__(16) int   g_starts[NG];
__device__ __align__(16) float g_seq0[(size_t)NG * TLEN * HG];      // 33.5 MB
__device__ __align__(16) float g_h0[(size_t)NG * TLEN * 64];        // 134 MB
__device__ __align__(16) float g_pre[(size_t)2 * NG * TLEN * 128];  // 537 MB
__device__ __align__(16) float g_pooled[NG * 64];

// ------------------------- helpers ------------------------------------------
__device__ __forceinline__ ull pk2(float lo, float hi) {
    ull v; asm("mov.b64 %0, {%1, %2};" : "=l"(v) : "f"(lo), "f"(hi)); return v;
}
__device__ __forceinline__ void upk2(ull v, float& lo, float& hi) {
    asm("mov.b64 {%0, %1}, %2;" : "=f"(lo), "=f"(hi) : "l"(v));
}
#define FMA2(d, a, b) asm("fma.rn.f32x2 %0, %1, %2, %0;" : "+l"(d) : "l"(a), "l"(b))

__device__ __forceinline__ float tanh_fast(float x) {
    float y; asm("tanh.approx.f32 %0, %1;" : "=f"(y) : "f"(x)); return y;
}
__device__ __forceinline__ float sig_fast(float x) {
    return fmaf(0.5f, tanh_fast(0.5f * x), 0.5f);
}

// ------------------------- init + degree + scan + fill -----------------------
__global__ void init_kernel() {
    int idx = blockIdx.x * 256 + threadIdx.x;
    if (idx < (int)(NG * TLEN * HG / 4))
        ((float4*)g_seq0)[idx] = make_float4(0.f, 0.f, 0.f, 0.f);
    if (idx < NN) g_degi[idx] = 0;
}

__global__ void deg_kernel(const int* __restrict__ dst, int E) {
    int e = blockIdx.x * 256 + threadIdx.x;
    if (e < E) atomicAdd(&g_degi[dst[e]], 1);
}

__global__ void scan1_kernel() {
    __shared__ int sh[256];
    int tid = threadIdx.x;
    sh[tid] = g_degi[blockIdx.x * 256 + tid];
    __syncthreads();
    for (int o = 128; o > 0; o >>= 1) {
        if (tid < o) sh[tid] += sh[tid + o];
        __syncthreads();
    }
    if (tid == 0) g_part[blockIdx.x] = sh[0];
}

__global__ void scan2_kernel() {
    __shared__ int sh[512];
    int tid = threadIdx.x;
    sh[tid] = g_part[tid];
    __syncthreads();
    int v;
    for (int o = 1; o < 512; o <<= 1) {
        v = (tid >= o) ? sh[tid - o] : 0;
        __syncthreads();
        sh[tid] += v;
        __syncthreads();
    }
    g_psum[tid] = (tid == 0) ? 0 : sh[tid - 1];
}

__global__ void scan3_kernel() {
    __shared__ int sh[256];
    int tid = threadIdx.x;
    int n = blockIdx.x * 256 + tid;
    int d = g_degi[n];
    sh[tid] = d;
    __syncthreads();
    int v;
    for (int o = 1; o < 256; o <<= 1) {
        v = (tid >= o) ? sh[tid - o] : 0;
        __syncthreads();
        sh[tid] += v;
        __syncthreads();
    }
    int off = g_psum[blockIdx.x] + sh[tid] - d;   // exclusive
    g_eoff[n] = off;
    g_ecur[n] = off;
    g_dinv[n] = rsqrtf((float)(d + 1));           // +1 self-loop
}

__global__ void fill_kernel(const int* __restrict__ src, const int* __restrict__ dst, int E) {
    int e = blockIdx.x * 256 + threadIdx.x;
    if (e >= E) return;
    int s = src[e], d = dst[e];
    int pos = atomicAdd(&g_ecur[d], 1);
    g_epk[pos] = make_int2(s, __float_as_int(g_dinv[s]));
}

// ------------------------- GCN feature transform -----------------------------
__global__ __launch_bounds__(256) void xw1_kernel(const float* __restrict__ x,
                                                  const float* __restrict__ W) {
    __shared__ float Ws[FIN * HG];
    __shared__ float Xs[16 * FIN];
    int tid = threadIdx.x;
    for (int i = tid; i < FIN * HG; i += 256) Ws[i] = W[i];
    size_t base = (size_t)blockIdx.x * 16 * FIN;
    for (int i = tid; i < 16 * FIN; i += 256) Xs[i] = x[base + i];
    __syncthreads();
    int nl = tid >> 4, j = tid & 15;
    const float* xr = Xs + nl * FIN;
    float acc = 0.f;
#pragma unroll
    for (int d = 0; d < FIN; d++) acc = fmaf(xr[d], Ws[d * HG + j], acc);
    g_xw[(size_t)blockIdx.x * 256 + tid] = acc;
}

__global__ __launch_bounds__(256) void xw2_kernel(const float* __restrict__ W) {
    __shared__ float Ws[HG * HG];
    __shared__ float Xs[16 * HG];
    int tid = threadIdx.x;
    if (tid < HG * HG) Ws[tid] = W[tid];
    size_t base = (size_t)blockIdx.x * 16 * HG;
    if (tid < 64) ((float4*)Xs)[tid] = ((const float4*)(g_agg + base))[tid];
    __syncthreads();
    int nl = tid >> 4, j = tid & 15;
    const float* xr = Xs + nl * HG;
    float acc = 0.f;
#pragma unroll
    for (int d = 0; d < HG; d++) acc = fmaf(fmaxf(xr[d], 0.f), Ws[d * HG + j], acc);
    g_xw[(size_t)blockIdx.x * 256 + tid] = acc;
}

// ------------------------- gather-based conv (1 thread / node) ---------------
__global__ __launch_bounds__(256) void conv_kernel(const float* __restrict__ bias) {
    int n = blockIdx.x * 256 + threadIdx.x;
    if (n >= NN) return;
    int e0 = g_eoff[n];
    int e1 = e0 + g_degi[n];
    float4 a0 = make_float4(0.f, 0.f, 0.f, 0.f), a1 = a0, a2 = a0, a3 = a0;
#pragma unroll 4
    for (int e = e0; e < e1; e++) {
        int2 pk = g_epk[e];
        int s = pk.x;
        float nr = __int_as_float(pk.y);
        const float4* xs = (const float4*)(g_xw + (size_t)s * HG);
        float4 v0 = xs[0], v1 = xs[1], v2 = xs[2], v3 = xs[3];
        a0.x = fmaf(nr, v0.x, a0.x); a0.y = fmaf(nr, v0.y, a0.y);
        a0.z = fmaf(nr, v0.z, a0.z); a0.w = fmaf(nr, v0.w, a0.w);
        a1.x = fmaf(nr, v1.x, a1.x); a1.y = fmaf(nr, v1.y, a1.y);
        a1.z = fmaf(nr, v1.z, a1.z); a1.w = fmaf(nr, v1.w, a1.w);
        a2.x = fmaf(nr, v2.x, a2.x); a2.y = fmaf(nr, v2.y, a2.y);
        a2.z = fmaf(nr, v2.z, a2.z); a2.w = fmaf(nr, v2.w, a2.w);
        a3.x = fmaf(nr, v3.x, a3.x); a3.y = fmaf(nr, v3.y, a3.y);
        a3.z = fmaf(nr, v3.z, a3.z); a3.w = fmaf(nr, v3.w, a3.w);
    }
    float di = g_dinv[n];
    float d2 = di * di;
    const float4* xn = (const float4*)(g_xw + (size_t)n * HG);
    const float4* bb = (const float4*)bias;
    float4* out = (float4*)(g_agg + (size_t)n * HG);
    float4 q, b, w;
#define EMIT(acc, k) \
    w = xn[k]; b = bb[k]; \
    q.x = b.x + di * acc.x + d2 * w.x; q.y = b.y + di * acc.y + d2 * w.y; \
    q.z = b.z + di * acc.z + d2 * w.z; q.w = b.w + di * acc.w + d2 * w.w; \
    out[k] = q;
    EMIT(a0, 0) EMIT(a1, 1) EMIT(a2, 2) EMIT(a3, 3)
#undef EMIT
}

// ------------------------- conv, pair-split variant (PROBE ONLY) -------------
// 2 threads per node, interleaved edges, shfl_xor(1) combine. Launched only
// at probe scale (same 8192 nodes R11's single-thread probe measured) for a
// direct A/B read in ncu. Output region fully overwritten by the real convs.
__global__ __launch_bounds__(256) void conv_pair_kernel(const float* __restrict__ bias) {
    int idx = blockIdx.x * 256 + threadIdx.x;
    int n = idx >> 1, par = idx & 1;
    if (n >= NN) return;
    int e0 = g_eoff[n];
    int e1 = e0 + g_degi[n];
    float4 a0 = make_float4(0.f, 0.f, 0.f, 0.f), a1 = a0, a2 = a0, a3 = a0;
#pragma unroll 4
    for (int e = e0 + par; e < e1; e += 2) {
        int2 pk = g_epk[e];
        int s = pk.x;
        float nr = __int_as_float(pk.y);
        const float4* xs = (const float4*)(g_xw + (size_t)s * HG);
        float4 v0 = xs[0], v1 = xs[1], v2 = xs[2], v3 = xs[3];
        a0.x = fmaf(nr, v0.x, a0.x); a0.y = fmaf(nr, v0.y, a0.y);
        a0.z = fmaf(nr, v0.z, a0.z); a0.w = fmaf(nr, v0.w, a0.w);
        a1.x = fmaf(nr, v1.x, a1.x); a1.y = fmaf(nr, v1.y, a1.y);
        a1.z = fmaf(nr, v1.z, a1.z); a1.w = fmaf(nr, v1.w, a1.w);
        a2.x = fmaf(nr, v2.x, a2.x); a2.y = fmaf(nr, v2.y, a2.y);
        a2.z = fmaf(nr, v2.z, a2.z); a2.w = fmaf(nr, v2.w, a2.w);
        a3.x = fmaf(nr, v3.x, a3.x); a3.y = fmaf(nr, v3.y, a3.y);
        a3.z = fmaf(nr, v3.z, a3.z); a3.w = fmaf(nr, v3.w, a3.w);
    }
#define CMB(f) f += __shfl_xor_sync(0xffffffffu, f, 1)
    CMB(a0.x); CMB(a0.y); CMB(a0.z); CMB(a0.w);
    CMB(a1.x); CMB(a1.y); CMB(a1.z); CMB(a1.w);
    CMB(a2.x); CMB(a2.y); CMB(a2.z); CMB(a2.w);
    CMB(a3.x); CMB(a3.y); CMB(a3.z); CMB(a3.w);
#undef CMB
    if (par) return;
    float di = g_dinv[n];
    float d2 = di * di;
    const float4* xn = (const float4*)(g_xw + (size_t)n * HG);
    const float4* bb = (const float4*)bias;
    float4* out = (float4*)(g_agg + (size_t)n * HG);
    float4 q, b, w;
#define EMIT(acc, k) \
    w = xn[k]; b = bb[k]; \
    q.x = b.x + di * acc.x + d2 * w.x; q.y = b.y + di * acc.y + d2 * w.y; \
    q.z = b.z + di * acc.z + d2 * w.z; q.w = b.w + di * acc.w + d2 * w.w; \
    out[k] = q;
    EMIT(a0, 0) EMIT(a1, 1) EMIT(a2, 2) EMIT(a3, 3)
#undef EMIT
}

// ------------------------- ragged -> padded ---------------------------------
__global__ void starts_kernel(const int* __restrict__ batch) {
    int i = blockIdx.x * 256 + threadIdx.x;
    if (i >= NN) return;
    int b = batch[i];
    int bp = (i == 0) ? -1 : batch[i - 1];
    for (int g = bp + 1; g <= b; ++g) g_starts[g] = i;   // batch is sorted
}

__global__ void pack_kernel(const int* __restrict__ batch) {
    int idx = blockIdx.x * 256 + threadIdx.x;
    if (idx >= NN * 4) return;
    int n = idx >> 2, q = idx & 3;
    int g = batch[n];
    int pos = n - g_starts[g];
    if (pos >= TLEN) return;  // mode="drop"
    float4 v = ((const float4*)(g_agg + (size_t)n * HG))[q];
    v.x = fmaxf(v.x, 0.f); v.y = fmaxf(v.y, 0.f);
    v.z = fmaxf(v.z, 0.f); v.w = fmaxf(v.w, 0.f);
    ((float4*)(g_seq0 + ((size_t)g * TLEN + pos) * HG))[q] = v;
}

// ------------------------- LSTM input projection (batch GEMM, FMA2) ----------
template<int DIN>
__global__ __launch_bounds__(256) void gemm_pre_kernel(
    const float* __restrict__ X,      // [NG][TLEN][DIN]
    const float* __restrict__ wih,    // [2][128][DIN]
    const float* __restrict__ bih, const float* __restrict__ bhh) // [2][128]
{
    constexpr int WPAD = DIN + 4;
    constexpr int TT = 64;
    constexpr int TPG = 8;
    __shared__ float Ws[128 * WPAD];
    __shared__ float Bs[128];
    __shared__ float Xs[TT * DIN];

    int dir = blockIdx.z, row = blockIdx.y;
    int tb = blockIdx.x * TT;
    int tid = threadIdx.x;

    const float* Wg = wih + (size_t)dir * 128 * DIN;
    for (int i = tid; i < 128 * DIN; i += 256) {
        int r = i / DIN, k = i - r * DIN;
        Ws[r * WPAD + k] = Wg[i];
    }
    if (tid < 128) Bs[tid] = bih[dir * 128 + tid] + bhh[dir * 128 + tid];
    const float4* Xg = (const float4*)(X + ((size_t)row * TLEN + tb) * DIN);
    for (int i = tid; i < TT * DIN / 4; i += 256) ((float4*)Xs)[i] = Xg[i];
    __syncthreads();

    int j = tid & 31, grp = tid >> 5;
    const float* xb = Xs + grp * TPG * DIN;
    const float* w0 = Ws + (0 * 32 + j) * WPAD;
    const float* w1 = Ws + (1 * 32 + j) * WPAD;
    const float* w2 = Ws + (2 * 32 + j) * WPAD;
    const float* w3 = Ws + (3 * 32 + j) * WPAD;

    ull acc[TPG][4];
#pragma unroll
    for (int tt = 0; tt < TPG; tt++)
#pragma unroll
        for (int g = 0; g < 4; g++) acc[tt][g] = 0ull;

#pragma unroll
    for (int k = 0; k < DIN; k += 4) {
        ulonglong2 wv0 = *(const ulonglong2*)(w0 + k);
        ulonglong2 wv1 = *(const ulonglong2*)(w1 + k);
        ulonglong2 wv2 = *(const ulonglong2*)(w2 + k);
        ulonglong2 wv3 = *(const ulonglong2*)(w3 + k);
#pragma unroll
        for (int tt = 0; tt < TPG; tt++) {
            ulonglong2 xv = *(const ulonglong2*)(xb + tt * DIN + k);
            FMA2(acc[tt][0], xv.x, wv0.x); FMA2(acc[tt][0], xv.y, wv0.y);
            FMA2(acc[tt][1], xv.x, wv1.x); FMA2(acc[tt][1], xv.y, wv1.y);
            FMA2(acc[tt][2], xv.x, wv2.x); FMA2(acc[tt][2], xv.y, wv2.y);
            FMA2(acc[tt][3], xv.x, wv3.x); FMA2(acc[tt][3], xv.y, wv3.y);
        }
    }

    float b0 = Bs[j], b1 = Bs[32 + j], b2 = Bs[64 + j], b3 = Bs[96 + j];
    float4* Og = (float4*)(g_pre + (((size_t)dir * NG + row) * TLEN + tb + grp * TPG) * 128) + j;
#pragma unroll
    for (int tt = 0; tt < TPG; tt++) {
        float lo, hi; float4 o;
        upk2(acc[tt][0], lo, hi); o.x = lo + hi + b0;
        upk2(acc[tt][1], lo, hi); o.y = lo + hi + b1;
        upk2(acc[tt][2], lo, hi); o.z = lo + hi + b2;
        upk2(acc[tt][3], lo, hi); o.w = lo + hi + b3;
        Og[(size_t)tt * 32] = o;
    }
}

// ------------------------- LSTM recurrence -----------------------------------
// One warp per (row, dir); thread j owns hidden unit j. 4-deep register
// prefetch ring on the DRAM-resident pre stream. Dual accumulators per gate
// halve the FMA2 dependency chain (8 deep instead of 16) on the serial path.
template<bool IS_L0>
__global__ __launch_bounds__(32) void lstm_rec_kernel(const float* __restrict__ whh)
{
    int row = blockIdx.x, dir = blockIdx.y;
    int j = threadIdx.x;
    const float4* P = (const float4*)(g_pre + ((size_t)dir * NG + row) * TLEN * 128) + j;
    float* O = g_h0 + (size_t)row * TLEN * 64 + dir * 32 + j;

    ulonglong2 w[4][8];
#pragma unroll
    for (int g = 0; g < 4; g++) {
        const ulonglong2* wp = (const ulonglong2*)(whh + ((size_t)dir * 128 + g * 32 + j) * 32);
#pragma unroll
        for (int q = 0; q < 8; q++) w[g][q] = wp[q];
    }

    __shared__ __align__(16) float h_s[2][32];
    h_s[0][j] = 0.f;
    __syncwarp();

    int t0 = dir ? (TLEN - 1) : 0;
    int dt = dir ? -1 : 1;
    float c = 0.f, pool = 0.f;
    int buf = 0;

#define LOADP(s_) P[(size_t)(t0 + (s_) * dt) * 32]

#define STEP(pp, s_) { \
    ull a0 = pk2(pp.x, 0.f), a1 = pk2(pp.y, 0.f); \
    ull a2 = pk2(pp.z, 0.f), a3 = pk2(pp.w, 0.f); \
    ull b0 = 0ull, b1 = 0ull, b2 = 0ull, b3 = 0ull; \
    const ulonglong2* hv = (const ulonglong2*)h_s[buf]; \
    _Pragma("unroll") \
    for (int q = 0; q < 8; q++) { \
        ulonglong2 hh = hv[q]; \
        if (q < 4) { \
            FMA2(a0, hh.x, w[0][q].x); FMA2(a0, hh.y, w[0][q].y); \
            FMA2(a1, hh.x, w[1][q].x); FMA2(a1, hh.y, w[1][q].y); \
            FMA2(a2, hh.x, w[2][q].x); FMA2(a2, hh.y, w[2][q].y); \
            FMA2(a3, hh.x, w[3][q].x); FMA2(a3, hh.y, w[3][q].y); \
        } else { \
            FMA2(b0, hh.x, w[0][q].x); FMA2(b0, hh.y, w[0][q].y); \
            FMA2(b1, hh.x, w[1][q].x); FMA2(b1, hh.y, w[1][q].y); \
            FMA2(b2, hh.x, w[2][q].x); FMA2(b2, hh.y, w[2][q].y); \
            FMA2(b3, hh.x, w[3][q].x); FMA2(b3, hh.y, w[3][q].y); \
        } \
    } \
    float lo, hi, lo2, hi2; \
    upk2(a0, lo, hi); upk2(b0, lo2, hi2); float gi = sig_fast((lo + hi) + (lo2 + hi2)); \
    upk2(a1, lo, hi); upk2(b1, lo2, hi2); float gf = sig_fast((lo + hi) + (lo2 + hi2)); \
    upk2(a2, lo, hi); upk2(b2, lo2, hi2); float gg = tanh_fast((lo + hi) + (lo2 + hi2)); \
    upk2(a3, lo, hi); upk2(b3, lo2, hi2); float go = sig_fast((lo + hi) + (lo2 + hi2)); \
    c = gf * c + gi * gg; \
    float h = go * tanh_fast(c); \
    if (IS_L0) O[(size_t)(t0 + (s_) * dt) * 64] = h; \
    else       pool += h; \
    h_s[buf ^ 1][j] = h; \
    __syncwarp(); \
    buf ^= 1; }

    float4 p0 = LOADP(0);
    float4 p1 = LOADP(1);
    float4 p2 = LOADP(2);
    for (int s = 0; s < TLEN; s += 4) {
        float4 p3 = (s + 3 < TLEN) ? LOADP(s + 3) : p0;
        STEP(p0, s)
        float4 q0 = (s + 4 < TLEN) ? LOADP(s + 4) : p0;
        STEP(p1, s + 1)
        float4 q1 = (s + 5 < TLEN) ? LOADP(s + 5) : p0;
        STEP(p2, s + 2)
        float4 q2 = (s + 6 < TLEN) ? LOADP(s + 6) : p0;
        STEP(p3, s + 3)
        p0 = q0; p1 = q1; p2 = q2;
    }
#undef STEP
#undef LOADP
    if (!IS_L0) g_pooled[row * 64 + dir * 32 + j] = pool;
}

// ------------------------- FC + mean ----------------------------------------
__global__ void fc_kernel(const float* __restrict__ w, const float* __restrict__ b,
                          float* __restrict__ out) {
    int idx = blockIdx.x * 256 + threadIdx.x;
    if (idx >= NG * NCLS) return;
    int r = idx / NCLS, cc = idx - r * NCLS;
    const float* p = g_pooled + r * 64;
    float acc = 0.f;
#pragma unroll
    for (int k = 0; k < 64; k++) acc += p[k] * w[k * NCLS + cc];
    out[idx] = b[cc] + acc * (1.f / (float)TLEN);
}

// ------------------------- launch -------------------------------------------
extern "C" void kernel_launch(void* const* d_in, const int* in_sizes, int n_in,
                              void* d_out, int out_size) {
    const float* x     = (const float*)d_in[0];
    const int*   ei    = (const int*)d_in[1];
    const int*   batch = (const int*)d_in[2];
    const float* w1    = (const float*)d_in[3];
    const float* b1    = (const float*)d_in[4];
    const float* w2    = (const float*)d_in[5];
    const float* b2    = (const float*)d_in[6];
    const float* l0wih = (const float*)d_in[7];
    const float* l0whh = (const float*)d_in[8];
    const float* l0bih = (const float*)d_in[9];
    const float* l0bhh = (const float*)d_in[10];
    const float* l1wih = (const float*)d_in[11];
    const float* l1whh = (const float*)d_in[12];
    const float* l1bih = (const float*)d_in[13];
    const float* l1bhh = (const float*)d_in[14];
    const float* fcw   = (const float*)d_in[15];
    const float* fcb   = (const float*)d_in[16];
    float* out = (float*)d_out;

    int E = in_sizes[1] / 2;
    const int* src = ei;
    const int* dst = ei + E;

    float* seq0_p; cudaGetSymbolAddress((void**)&seq0_p, g_seq0);
    float* h0_p;   cudaGetSymbolAddress((void**)&h0_p, g_h0);

    // CSR build
    init_kernel<<<8192, 256>>>();                          // launch 0
    deg_kernel<<<(E + 255) / 256, 256>>>(dst, E);          // launch 1
    scan1_kernel<<<512, 256>>>();                          // launch 2

    // PROBE (launch 3 = the one ncu profiles): pair-split conv over the SAME
    // 8192 nodes R11's single-thread probe measured (15.97us). Direct A/B of
    // the two conv variants. Uses stale-but-deterministic CSR/xw; its g_agg
    // writes are fully overwritten by the real convs below.
    conv_pair_kernel<<<64, 256>>>(b1);

    scan2_kernel<<<1, 512>>>();                            // launch 4
    scan3_kernel<<<512, 256>>>();                          // launch 5
    fill_kernel<<<(E + 255) / 256, 256>>>(src, dst, E);

    // conv1 + conv2 (gather-based, single thread per node — known-best)
    xw1_kernel<<<NN / 16, 256>>>(x, w1);
    conv_kernel<<<NN / 256, 256>>>(b1);
    xw2_kernel<<<NN / 16, 256>>>(w2);
    conv_kernel<<<NN / 256, 256>>>(b2);

    // pack
    starts_kernel<<<(NN + 255) / 256, 256>>>(batch);
    pack_kernel<<<(NN * 4 + 255) / 256, 256>>>(batch);

    // BiLSTM layer 0 (FMA2 tiled GEMM — known-best — + 1-warp recurrence)
    gemm_pre_kernel<HG><<<dim3(TLEN / 64, NG, 2), 256>>>(seq0_p, l0wih, l0bih, l0bhh);
    lstm_rec_kernel<true><<<dim3(NG, 2), 32>>>(l0whh);

    // BiLSTM layer 1 (fuses mean pooling)
    gemm_pre_kernel<64><<<dim3(TLEN / 64, NG, 2), 256>>>(h0_p, l1wih, l1bih, l1bhh);
    lstm_rec_kernel<false><<<dim3(NG, 2), 32>>>(l1whh);

    fc_kernel<<<(NG * NCLS + 255) / 256, 256>>>(fcw, fcb, out);
}